// round 2
// baseline (speedup 1.0000x reference)
#include <cuda_runtime.h>

#define NN 8
#define CC 19
#define HW (512*512)
#define HW4 (HW/4)
#define TOTAL4 (NN*HW4)      // 524288 float4-pixels
#define TPB 256

// ---- persistent device scratch (no allocations allowed) ----
__device__ unsigned g_bar, g_done;
__device__ int    g_hseg[NN][CC], g_hatt[NN][CC];
__device__ int    g_pos, g_neg;
__device__ double g_bce_pos, g_bce_neg;
__device__ double g_seg_num[NN], g_seg_den[NN], g_att_num[NN], g_att_den[NN];
__device__ unsigned char g_pk[NN * HW];   // 2 MB packed: class(5b) | att<<5

__global__ void k_init() {
    const int i = threadIdx.x;
    if (i < NN) { g_seg_num[i]=0.0; g_seg_den[i]=0.0; g_att_num[i]=0.0; g_att_den[i]=0.0; }
    if (i == 0) { g_bce_pos = 0.0; g_bce_neg = 0.0; g_pos = 0; g_neg = 0; g_bar = 0; g_done = 0; }
    for (int j = i; j < NN*CC; j += blockDim.x) {
        ((int*)g_hseg)[j] = 0;
        ((int*)g_hatt)[j] = 0;
    }
}

// block-reduce 4 floats (8 warps), result valid on (warp0, lane0)
__device__ __forceinline__ void block_reduce4(float& v0, float& v1, float& v2, float& v3,
                                              float (*red)[4]) {
    #pragma unroll
    for (int off = 16; off; off >>= 1) {
        v0 += __shfl_down_sync(0xffffffffu, v0, off);
        v1 += __shfl_down_sync(0xffffffffu, v1, off);
        v2 += __shfl_down_sync(0xffffffffu, v2, off);
        v3 += __shfl_down_sync(0xffffffffu, v3, off);
    }
    const int lane = threadIdx.x & 31, wrp = threadIdx.x >> 5;
    if (lane == 0) { red[wrp][0]=v0; red[wrp][1]=v1; red[wrp][2]=v2; red[wrp][3]=v3; }
    __syncthreads();
    if (wrp == 0) {
        v0 = (lane < TPB/32) ? red[lane][0] : 0.f;
        v1 = (lane < TPB/32) ? red[lane][1] : 0.f;
        v2 = (lane < TPB/32) ? red[lane][2] : 0.f;
        v3 = (lane < TPB/32) ? red[lane][3] : 0.f;
        #pragma unroll
        for (int off = 4; off; off >>= 1) {
            v0 += __shfl_down_sync(0xffffffffu, v0, off);
            v1 += __shfl_down_sync(0xffffffffu, v1, off);
            v2 += __shfl_down_sync(0xffffffffu, v2, off);
            v3 += __shfl_down_sync(0xffffffffu, v3, off);
        }
    }
}

__global__ void __launch_bounds__(TPB) k_fused(const float* __restrict__ segin,
                                               const float* __restrict__ edgein,
                                               const int*   __restrict__ segmask,
                                               const int*   __restrict__ edgemask,
                                               float* __restrict__ out,
                                               int nblocks) {
    const int tid = threadIdx.x;
    const int gsz = nblocks * TPB;

    __shared__ int   shseg[NN][CC], shatt[NN][CC];
    __shared__ float swseg[NN][CC], swatt[NN][CC];
    __shared__ float red[TPB/32][4];

    for (int j = tid; j < NN*CC; j += TPB) { ((int*)shseg)[j] = 0; ((int*)shatt)[j] = 0; }
    __syncthreads();

    // ================= PHASE 1: aux pass (hist + BCE partials + packed bytes) =====
    float bp = 0.f, bn = 0.f; int cp = 0, cn = 0;
    for (int i = blockIdx.x * TPB + tid; i < TOTAL4; i += gsz) {
        const int n = i >> 16;                              // HW4 = 65536
        const int4   t4 = ((const int4*  )segmask )[i];
        const float4 e4 = ((const float4*)edgein  )[i];
        const int4   m4 = ((const int4*  )edgemask)[i];
        uchar4 pk;
        #define P1(tj, ej, mj, pkj)                                            \
        {                                                                      \
            const bool att = (ej) > 0.8f;                                      \
            if ((unsigned)(tj) < CC) {                                         \
                atomicAdd(&shseg[n][tj], 1);                                   \
                if (att) atomicAdd(&shatt[n][tj], 1);                          \
                pkj = (unsigned char)((tj) | (att ? 32 : 0));                  \
            } else pkj = 31;                                                   \
            const float bce = fmaxf(ej, 0.f) - (ej) * (float)(mj)              \
                            + log1pf(__expf(-fabsf(ej)));                      \
            if ((mj) == 1)      { bp += bce; cp++; }                           \
            else if ((mj) == 0) { bn += bce; cn++; }                           \
        }
        P1(t4.x, e4.x, m4.x, pk.x)
        P1(t4.y, e4.y, m4.y, pk.y)
        P1(t4.z, e4.z, m4.z, pk.z)
        P1(t4.w, e4.w, m4.w, pk.w)
        #undef P1
        ((uchar4*)g_pk)[i] = pk;
    }
    // flush BCE partials
    {
        float v0 = bp, v1 = bn, v2 = (float)cp, v3 = (float)cn;
        __syncthreads();
        block_reduce4(v0, v1, v2, v3, red);
        if (tid == 0) {
            atomicAdd(&g_bce_pos, (double)v0);
            atomicAdd(&g_bce_neg, (double)v1);
            atomicAdd(&g_pos, (int)v2);
            atomicAdd(&g_neg, (int)v3);
        }
    }
    __syncthreads();
    // flush histograms
    for (int j = tid; j < NN*CC; j += TPB) {
        const int s = ((int*)shseg)[j], a = ((int*)shatt)[j];
        if (s) atomicAdd(&((int*)g_hseg)[j], s);
        if (a) atomicAdd(&((int*)g_hatt)[j], a);
    }

    // ================= GRID BARRIER ==============================================
    __syncthreads();
    if (tid == 0) {
        __threadfence();
        atomicAdd(&g_bar, 1u);
        while (*(volatile unsigned*)&g_bar < (unsigned)nblocks) { __nanosleep(64); }
        __threadfence();
    }
    __syncthreads();

    // ================= compute weights (redundant per block, into shared) ========
    {
        __shared__ float tot_s[NN], tot_a[NN];
        if (tid < NN) {
            int s = 0, a = 0;
            #pragma unroll
            for (int c = 0; c < CC; c++) { s += g_hseg[tid][c]; a += g_hatt[tid][c]; }
            tot_s[tid] = fmaxf((float)s, 1.0f);
            tot_a[tid] = fmaxf((float)a, 1.0f);
        }
        __syncthreads();
        if (tid < NN*CC) {
            const int n = tid / CC, c = tid % CC;
            const int cs = g_hseg[n][c], ca = g_hatt[n][c];
            swseg[n][c] = (cs > 0 ? (1.0f - (float)cs / tot_s[n]) : 0.0f) + 1.0f;
            swatt[n][c] = (ca > 0 ? (1.0f - (float)ca / tot_a[n]) : 0.0f) + 1.0f;
        }
        __syncthreads();
    }

    // ================= PHASE 2: segin pass (lse + weighted NLL, seg & att) =======
    for (int i = blockIdx.x * TPB + tid; i < TOTAL4; i += gsz) {
        const int n = i >> 16;                    // uniform across the block (chunks aligned)
        const int p = i & 0xFFFF;
        const uchar4 pk4 = ((const uchar4*)g_pk)[i];
        const int pk[4] = { pk4.x, pk4.y, pk4.z, pk4.w };

        float se[4] = {0.f, 0.f, 0.f, 0.f};
        float xt[4] = {0.f, 0.f, 0.f, 0.f};
        const float4* base = (const float4*)(segin + (size_t)n * CC * HW) + p;
        #pragma unroll
        for (int c = 0; c < CC; c++) {
            const float4 v = base[(size_t)c * HW4];
            se[0] += __expf(v.x); if ((pk[0] & 31) == c) xt[0] = v.x;
            se[1] += __expf(v.y); if ((pk[1] & 31) == c) xt[1] = v.y;
            se[2] += __expf(v.z); if ((pk[2] & 31) == c) xt[2] = v.z;
            se[3] += __expf(v.w); if ((pk[3] & 31) == c) xt[3] = v.w;
        }

        float seg_num = 0.f, seg_den = 0.f, att_num = 0.f, att_den = 0.f;
        #pragma unroll
        for (int j = 0; j < 4; j++) {
            const int tc = pk[j] & 31;
            if (tc < CC) {
                const float nlp = __logf(se[j]) - xt[j];
                const float w = swseg[n][tc];
                seg_num += w * nlp;
                seg_den += w;
                if (pk[j] & 32) {
                    const float wa = swatt[n][tc];
                    att_num += wa * nlp;
                    att_den += wa;
                }
            }
        }
        __syncthreads();
        block_reduce4(seg_num, seg_den, att_num, att_den, red);
        if (tid == 0) {
            atomicAdd(&g_seg_num[n], (double)seg_num);
            atomicAdd(&g_seg_den[n], (double)seg_den);
            atomicAdd(&g_att_num[n], (double)att_num);
            atomicAdd(&g_att_den[n], (double)att_den);
        }
        __syncthreads();
    }

    // ================= last block writes the output ==============================
    if (tid == 0) {
        __threadfence();
        const unsigned done = atomicAdd(&g_done, 1u);
        if (done == (unsigned)nblocks - 1) {
            double seg = 0.0, att = 0.0;
            #pragma unroll
            for (int n = 0; n < NN; n++) {
                seg += g_seg_num[n] / fmax(g_seg_den[n], 1e-12);
                att += g_att_num[n] / fmax(g_att_den[n], 1e-12);
            }
            const double p = (double)g_pos, q = (double)g_neg;
            const double s = fmax(p + q, 1.0);
            const double bce = (q / s) * g_bce_pos + (p / s) * g_bce_neg;
            out[0] = (float)seg;
            out[1] = (float)(20.0 * bce / (double)((long long)NN * HW));
            out[2] = (float)att;
            out[3] = 0.0f;
        }
    }
}

extern "C" void kernel_launch(void* const* d_in, const int* in_sizes, int n_in,
                              void* d_out, int out_size) {
    const float* segin    = (const float*)d_in[0];
    const float* edgein   = (const float*)d_in[1];
    const int*   segmask  = (const int*)  d_in[2];
    const int*   edgemask = (const int*)  d_in[3];

    int dev = 0;
    cudaGetDevice(&dev);
    int nsm = 148;
    cudaDeviceGetAttribute(&nsm, cudaDevAttrMultiProcessorCount, dev);
    int maxb = 0;
    cudaOccupancyMaxActiveBlocksPerMultiprocessor(&maxb, k_fused, TPB, 0);
    if (maxb < 1) maxb = 1;
    int nblocks = nsm * maxb;
    if (nblocks > TOTAL4 / TPB) nblocks = TOTAL4 / TPB;   // never more blocks than chunks

    k_init<<<1, 256>>>();
    k_fused<<<nblocks, TPB>>>(segin, edgein, segmask, edgemask, (float*)d_out, nblocks);
}